// round 1
// baseline (speedup 1.0000x reference)
#include <cuda_runtime.h>

#define B_     32
#define T_     512
#define D_     384
#define MAXOUT 3584            // T_ * (8 - 1)
#define VEC    (D_ / 4)        // 96 float4 per row

// Scratch: index map from output position -> source frame (-1 = zero fill).
__device__ int g_idx_map[B_ * MAXOUT];

// One block per batch, 512 threads (one per source frame).
__global__ void __launch_bounds__(T_) build_idx_kernel(const int* __restrict__ dur)
{
    const int b = blockIdx.x;
    const int t = threadIdx.x;

    int d = dur[b * T_ + t];
    if (d < 0) d = 0;

    // Inclusive block scan: warp shuffle scan + cross-warp combine.
    const int lane = t & 31;
    const int warp = t >> 5;
    int v = d;
    #pragma unroll
    for (int o = 1; o < 32; o <<= 1) {
        int n = __shfl_up_sync(0xffffffffu, v, o);
        if (lane >= o) v += n;
    }
    __shared__ int wsum[16];
    if (lane == 31) wsum[warp] = v;
    __syncthreads();
    if (warp == 0 && lane < 16) {
        int w = wsum[lane];
        #pragma unroll
        for (int o = 1; o < 16; o <<= 1) {
            int n = __shfl_up_sync(0x0000ffffu, w, o);
            if (lane >= o) w += n;
        }
        wsum[lane] = w;
    }
    __syncthreads();

    const int cum   = v + (warp > 0 ? wsum[warp - 1] : 0);
    const int start = cum - d;

    int* __restrict__ row = g_idx_map + b * MAXOUT;
    for (int p = start; p < cum; ++p)
        row[p] = t;

    __shared__ int s_total;
    if (t == T_ - 1) s_total = cum;
    __syncthreads();
    const int total = s_total;
    for (int p = total + t; p < MAXOUT; p += T_)
        row[p] = -1;
}

// One thread per float4 of output. Grid sized to cover exactly B*MAXOUT*VEC.
__global__ void __launch_bounds__(256) gather_kernel(const float4* __restrict__ in,
                                                     float4* __restrict__ out)
{
    const int gid = blockIdx.x * blockDim.x + threadIdx.x;
    const int n   = B_ * MAXOUT * VEC;
    if (gid >= n) return;

    const int row = gid / VEC;           // b * MAXOUT + pos
    const int c   = gid - row * VEC;
    const int b   = row / MAXOUT;

    const int idx = g_idx_map[row];

    float4 val = make_float4(0.f, 0.f, 0.f, 0.f);
    if (idx >= 0)
        val = in[(b * T_ + idx) * VEC + c];
    out[gid] = val;
}

extern "C" void kernel_launch(void* const* d_in, const int* in_sizes, int n_in,
                              void* d_out, int out_size)
{
    const float* x   = (const float*)d_in[0];   // [B, T, D] float32
    const int*   dur = (const int*)d_in[1];     // [B, T] int32
    float* out = (float*)d_out;                 // [B, MAXOUT, D] float32

    build_idx_kernel<<<B_, T_>>>(dur);

    const int n_vec  = B_ * MAXOUT * VEC;       // 11,010,048
    const int threads = 256;
    const int blocks  = (n_vec + threads - 1) / threads;  // 43008
    gather_kernel<<<blocks, threads>>>((const float4*)x, (float4*)out);
}

// round 2
// speedup vs baseline: 1.2638x; 1.2638x over previous
#include <cuda_runtime.h>

#define B_     32
#define T_     512
#define D_     384
#define MAXOUT 3584            // T_ * (8 - 1)
#define VEC    (D_ / 4)        // 96 float4 per row
#define UNROLL 4

// Scratch: index map from output position -> source frame (-1 = zero fill).
__device__ int g_idx_map[B_ * MAXOUT];

// One block per batch, 512 threads (one per source frame).
__global__ void __launch_bounds__(T_) build_idx_kernel(const int* __restrict__ dur)
{
    const int b = blockIdx.x;
    const int t = threadIdx.x;

    int d = dur[b * T_ + t];
    if (d < 0) d = 0;

    // Inclusive block scan: warp shuffle scan + cross-warp combine.
    const int lane = t & 31;
    const int warp = t >> 5;
    int v = d;
    #pragma unroll
    for (int o = 1; o < 32; o <<= 1) {
        int n = __shfl_up_sync(0xffffffffu, v, o);
        if (lane >= o) v += n;
    }
    __shared__ int wsum[16];
    if (lane == 31) wsum[warp] = v;
    __syncthreads();
    if (warp == 0 && lane < 16) {
        int w = wsum[lane];
        #pragma unroll
        for (int o = 1; o < 16; o <<= 1) {
            int n = __shfl_up_sync(0x0000ffffu, w, o);
            if (lane >= o) w += n;
        }
        wsum[lane] = w;
    }
    __syncthreads();

    const int cum   = v + (warp > 0 ? wsum[warp - 1] : 0);
    const int start = cum - d;

    int* __restrict__ row = g_idx_map + b * MAXOUT;
    for (int p = start; p < cum; ++p)
        row[p] = t;

    __shared__ int s_total;
    if (t == T_ - 1) s_total = cum;
    __syncthreads();
    const int total = s_total;
    for (int p = total + t; p < MAXOUT; p += T_)
        row[p] = -1;
}

// UNROLL independent (idx, gather, store) triples per thread, block-strided so
// every access is fully coalesced. n = B_*MAXOUT*VEC = 11,010,048 is exactly
// divisible by (256 * 10752) * 4, so no bounds checks needed.
__global__ void __launch_bounds__(256) gather_kernel(const float4* __restrict__ in,
                                                     float4* __restrict__ out)
{
    const int gid    = blockIdx.x * blockDim.x + threadIdx.x;
    const int stride = gridDim.x * blockDim.x;   // 2,752,512

    int  pos[UNROLL];
    int  idx[UNROLL];
    int  b_ [UNROLL];
    int  c_ [UNROLL];

    #pragma unroll
    for (int j = 0; j < UNROLL; ++j) {
        pos[j]      = gid + j * stride;
        const int r = pos[j] / VEC;              // b * MAXOUT + out_row
        c_[j]       = pos[j] - r * VEC;
        b_[j]       = r / MAXOUT;
        idx[j]      = __ldg(&g_idx_map[r]);      // warp-broadcast, L1 hit
    }

    float4 val[UNROLL];
    #pragma unroll
    for (int j = 0; j < UNROLL; ++j) {
        val[j] = make_float4(0.f, 0.f, 0.f, 0.f);
        if (idx[j] >= 0)
            val[j] = __ldg(&in[(b_[j] * T_ + idx[j]) * VEC + c_[j]]);
    }

    #pragma unroll
    for (int j = 0; j < UNROLL; ++j)
        out[pos[j]] = val[j];
}

extern "C" void kernel_launch(void* const* d_in, const int* in_sizes, int n_in,
                              void* d_out, int out_size)
{
    const float* x   = (const float*)d_in[0];   // [B, T, D] float32
    const int*   dur = (const int*)d_in[1];     // [B, T] int32
    float* out = (float*)d_out;                 // [B, MAXOUT, D] float32

    build_idx_kernel<<<B_, T_>>>(dur);

    const int n_vec   = B_ * MAXOUT * VEC;                      // 11,010,048
    const int threads = 256;
    const int blocks  = n_vec / (threads * UNROLL);             // 10752, exact
    gather_kernel<<<blocks, threads>>>((const float4*)x, (float4*)out);
}

// round 3
// speedup vs baseline: 1.3843x; 1.0954x over previous
#include <cuda_runtime.h>

#define B_      32
#define T_      512
#define D_      384
#define MAXOUT  3584                    // T_ * (8 - 1)
#define VEC     (D_ / 4)                // 96 float4 per row
#define THREADS 256
#define UNROLL  8
#define F4_PER_BATCH (MAXOUT * VEC)     // 344064
#define F4_PER_BLOCK (THREADS * UNROLL) // 2048
#define BLOCKS_PER_BATCH (F4_PER_BATCH / F4_PER_BLOCK) // 168, exact

// Fully fused: each block recomputes its batch's duration cumsum (cheap, L2-hot),
// maps its 2048 contiguous output float4s to source frames via smem binary
// search, and streams the gathered data out. No scratch globals, one launch.
__global__ void __launch_bounds__(THREADS) lr_fused_kernel(
    const int*    __restrict__ dur,
    const float4* __restrict__ in,
    float4*       __restrict__ out)
{
    __shared__ int cum[T_];
    __shared__ int wsum[8];

    const int tid = threadIdx.x;
    const int b   = blockIdx.y;

    // ── Per-block recomputed inclusive scan of this batch's 512 durations ──
    // Each thread owns elements (2*tid, 2*tid+1) via one coalesced int2 load.
    const int2 dp = ((const int2*)(dur + b * T_))[tid];
    const int  d0 = max(dp.x, 0);
    const int  d1 = max(dp.y, 0);

    const int lane = tid & 31;
    const int warp = tid >> 5;

    int v = d0 + d1;                        // pair sum
    #pragma unroll
    for (int o = 1; o < 32; o <<= 1) {
        int n = __shfl_up_sync(0xffffffffu, v, o);
        if (lane >= o) v += n;
    }
    if (lane == 31) wsum[warp] = v;
    __syncthreads();
    if (warp == 0) {
        int w = (lane < 8) ? wsum[lane] : 0;
        #pragma unroll
        for (int o = 1; o < 8; o <<= 1) {
            int n = __shfl_up_sync(0xffffffffu, w, o);
            if (lane >= o) w += n;
        }
        if (lane < 8) wsum[lane] = w;
    }
    __syncthreads();

    const int incl = v + (warp > 0 ? wsum[warp - 1] : 0);
    cum[2 * tid + 1] = incl;
    cum[2 * tid]     = incl - d1;
    __syncthreads();

    const int total = cum[T_ - 1];

    // ── Gather/stream this block's 2048 contiguous output float4s ──
    const int posb = blockIdx.x * F4_PER_BLOCK + tid;  // float4 idx within batch
    const float4* __restrict__ inb  = in  + b * (T_ * VEC);
    float4*       __restrict__ outb = out + b * F4_PER_BATCH;

    int row[UNROLL], col[UNROLL], idx[UNROLL];
    #pragma unroll
    for (int j = 0; j < UNROLL; ++j) {
        const int pos = posb + j * THREADS;
        row[j] = pos / VEC;                 // output row 0..3583
        col[j] = pos - row[j] * VEC;
        // searchsorted(cum, row, 'right'): count of cum[t] <= row.
        // Warp-uniform for (almost) all lanes -> LDS broadcast.
        int p = 0;
        #pragma unroll
        for (int step = 256; step > 0; step >>= 1)
            if (cum[p + step - 1] <= row[j]) p += step;
        idx[j] = min(p, T_ - 1);
    }

    float4 val[UNROLL];
    #pragma unroll
    for (int j = 0; j < UNROLL; ++j) {
        val[j] = make_float4(0.f, 0.f, 0.f, 0.f);
        if (row[j] < total)
            val[j] = __ldg(&inb[idx[j] * VEC + col[j]]);
    }

    #pragma unroll
    for (int j = 0; j < UNROLL; ++j)
        __stcs(&outb[posb + j * THREADS], val[j]);   // streaming: keep input in L2
}

extern "C" void kernel_launch(void* const* d_in, const int* in_sizes, int n_in,
                              void* d_out, int out_size)
{
    const float* x   = (const float*)d_in[0];   // [B, T, D] float32
    const int*   dur = (const int*)d_in[1];     // [B, T] int32
    float* out = (float*)d_out;                 // [B, MAXOUT, D] float32

    dim3 grid(BLOCKS_PER_BATCH, B_);
    lr_fused_kernel<<<grid, THREADS>>>(dur, (const float4*)x, (float4*)out);
}

// round 4
// speedup vs baseline: 1.5630x; 1.1291x over previous
#include <cuda_runtime.h>

#define B_      32
#define T_      512
#define D_      384
#define MAXOUT  3584                    // T_ * (8 - 1)
#define VEC     (D_ / 4)                // 96 float4 per row
#define THREADS 256
#define UNROLL  8
#define F4_PER_BATCH (MAXOUT * VEC)     // 344064
#define F4_PER_BLOCK (THREADS * UNROLL) // 2048
#define BLOCKS_PER_BATCH (F4_PER_BATCH / F4_PER_BLOCK) // 168, exact
#define NROWS   24                      // max distinct output rows per block (22) + pad

__global__ void __launch_bounds__(THREADS) lr_fused_kernel(
    const int*    __restrict__ dur,
    const float4* __restrict__ in,
    float4*       __restrict__ out)
{
    __shared__ int cum[T_];
    __shared__ int wsum[8];
    __shared__ int s_idx[NROWS];        // source frame per local output row (-1 = zero)

    const int tid = threadIdx.x;
    const int b   = blockIdx.y;

    // ── Per-block recomputed inclusive scan of this batch's 512 durations ──
    const int2 dp = ((const int2*)(dur + b * T_))[tid];
    const int  d0 = max(dp.x, 0);
    const int  d1 = max(dp.y, 0);

    const int lane = tid & 31;
    const int warp = tid >> 5;

    int v = d0 + d1;
    #pragma unroll
    for (int o = 1; o < 32; o <<= 1) {
        int n = __shfl_up_sync(0xffffffffu, v, o);
        if (lane >= o) v += n;
    }
    if (lane == 31) wsum[warp] = v;
    __syncthreads();
    if (warp == 0) {
        int w = (lane < 8) ? wsum[lane] : 0;
        #pragma unroll
        for (int o = 1; o < 8; o <<= 1) {
            int n = __shfl_up_sync(0xffffffffu, w, o);
            if (lane >= o) w += n;
        }
        if (lane < 8) wsum[lane] = w;
    }
    __syncthreads();

    const int incl = v + (warp > 0 ? wsum[warp - 1] : 0);
    cum[2 * tid + 1] = incl;
    cum[2 * tid]     = incl - d1;
    __syncthreads();

    const int total    = cum[T_ - 1];
    const int f4_base  = blockIdx.x * F4_PER_BLOCK;   // first float4 of this block
    const int row_base = f4_base / VEC;               // first output row touched

    // ── One binary search per distinct row, built by 24 threads ──
    if (tid < NROWS) {
        const int row = row_base + tid;
        int idx = -1;
        if (row < total) {
            int p = 0;
            #pragma unroll
            for (int step = 256; step > 0; step >>= 1)
                if (cum[p + step - 1] <= row) p += step;
            idx = min(p, T_ - 1);
        }
        s_idx[tid] = idx;
    }
    __syncthreads();

    // ── Stream 2048 contiguous float4s ──
    const int posb = f4_base + tid;
    const float4* __restrict__ inb  = in  + b * (T_ * VEC);
    float4*       __restrict__ outb = out + b * F4_PER_BATCH;

    if (row_base >= total) {
        // Entire block past the valid region: pure zero fill.
        const float4 z = make_float4(0.f, 0.f, 0.f, 0.f);
        #pragma unroll
        for (int j = 0; j < UNROLL; ++j)
            __stcs(&outb[posb + j * THREADS], z);
        return;
    }

    int idx[UNROLL], col[UNROLL];
    #pragma unroll
    for (int j = 0; j < UNROLL; ++j) {
        const int pos = posb + j * THREADS;
        const int row = pos / VEC;
        col[j] = pos - row * VEC;
        idx[j] = s_idx[row - row_base];   // broadcast LDS
    }

    float4 val[UNROLL];
    #pragma unroll
    for (int j = 0; j < UNROLL; ++j) {
        val[j] = make_float4(0.f, 0.f, 0.f, 0.f);
        if (idx[j] >= 0)
            val[j] = __ldg(&inb[idx[j] * VEC + col[j]]);
    }

    #pragma unroll
    for (int j = 0; j < UNROLL; ++j)
        __stcs(&outb[posb + j * THREADS], val[j]);
}

extern "C" void kernel_launch(void* const* d_in, const int* in_sizes, int n_in,
                              void* d_out, int out_size)
{
    const float* x   = (const float*)d_in[0];   // [B, T, D] float32
    const int*   dur = (const int*)d_in[1];     // [B, T] int32
    float* out = (float*)d_out;                 // [B, MAXOUT, D] float32

    dim3 grid(BLOCKS_PER_BATCH, B_);
    lr_fused_kernel<<<grid, THREADS>>>(dur, (const float4*)x, (float4*)out);
}

// round 5
// speedup vs baseline: 1.5774x; 1.0092x over previous
#include <cuda_runtime.h>

#define B_      32
#define T_      512
#define D_      384
#define MAXOUT  3584                    // T_ * (8 - 1)
#define VEC     (D_ / 4)                // 96 float4 per row
#define THREADS 256
#define UNROLL  8
#define F4_PER_BATCH (MAXOUT * VEC)     // 344064
#define F4_PER_BLOCK (THREADS * UNROLL) // 2048
#define BLOCKS_PER_BATCH (F4_PER_BATCH / F4_PER_BLOCK) // 168, exact
#define NROWS   24                      // distinct output rows per block (22) + pad

__global__ void __launch_bounds__(THREADS) lr_fused_kernel(
    const int*    __restrict__ dur,
    const float4* __restrict__ in,
    float4*       __restrict__ out)
{
    __shared__ int cum[T_];
    __shared__ int wsum[8];
    __shared__ int s_idx[NROWS];        // source frame per local output row (-1 = zero)

    const int tid = threadIdx.x;
    const int b   = blockIdx.y;

    // ── Per-block recomputed inclusive scan of this batch's 512 durations ──
    const int2 dp = ((const int2*)(dur + b * T_))[tid];
    const int  d0 = max(dp.x, 0);
    const int  d1 = max(dp.y, 0);

    const int lane = tid & 31;
    const int warp = tid >> 5;

    int v = d0 + d1;
    #pragma unroll
    for (int o = 1; o < 32; o <<= 1) {
        int n = __shfl_up_sync(0xffffffffu, v, o);
        if (lane >= o) v += n;
    }
    if (lane == 31) wsum[warp] = v;
    __syncthreads();
    if (warp == 0) {
        int w = (lane < 8) ? wsum[lane] : 0;
        #pragma unroll
        for (int o = 1; o < 8; o <<= 1) {
            int n = __shfl_up_sync(0xffffffffu, w, o);
            if (lane >= o) w += n;
        }
        if (lane < 8) wsum[lane] = w;
    }
    __syncthreads();

    const int incl = v + (warp > 0 ? wsum[warp - 1] : 0);
    cum[2 * tid + 1] = incl;
    cum[2 * tid]     = incl - d1;
    __syncthreads();

    const int total    = cum[T_ - 1];
    const int f4_base  = blockIdx.x * F4_PER_BLOCK;
    const int row_base = f4_base / VEC;

    // ── One binary search per distinct row ──
    if (tid < NROWS) {
        const int row = row_base + tid;
        int idx = -1;
        if (row < total) {
            int p = 0;
            #pragma unroll
            for (int step = 256; step > 0; step >>= 1)
                if (cum[p + step - 1] <= row) p += step;
            idx = min(p, T_ - 1);
        }
        s_idx[tid] = idx;
    }
    __syncthreads();

    const int posb = f4_base + tid;
    const float4* __restrict__ inb  = in  + b * (T_ * VEC);
    float4*       __restrict__ outb = out + b * F4_PER_BATCH;

    if (row_base >= total) {
        // Entire block past the valid region: pure zero fill.
        const float4 z = make_float4(0.f, 0.f, 0.f, 0.f);
        #pragma unroll
        for (int j = 0; j < UNROLL; ++j)
            __stcs(&outb[posb + j * THREADS], z);
        return;
    }

    int idx[UNROLL], col[UNROLL];
    #pragma unroll
    for (int j = 0; j < UNROLL; ++j) {
        const int pos = posb + j * THREADS;
        const int row = pos / VEC;
        col[j] = pos - row * VEC;
        idx[j] = s_idx[row - row_base];
    }

    // Unconditional clamped gathers: 8 fully independent LDG.128s.
    float4 val[UNROLL];
    #pragma unroll
    for (int j = 0; j < UNROLL; ++j) {
        const int ic = max(idx[j], 0);
        val[j] = __ldg(&inb[ic * VEC + col[j]]);
    }

    // Scheduling fence: no memory op crosses. Forces all 8 loads to issue
    // (and all 8 float4s to stay live in registers) before any store.
    asm volatile("" ::: "memory");

    #pragma unroll
    for (int j = 0; j < UNROLL; ++j) {
        float4 v4 = val[j];
        if (idx[j] < 0) v4 = make_float4(0.f, 0.f, 0.f, 0.f);
        __stcs(&outb[posb + j * THREADS], v4);
    }
}

extern "C" void kernel_launch(void* const* d_in, const int* in_sizes, int n_in,
                              void* d_out, int out_size)
{
    const float* x   = (const float*)d_in[0];   // [B, T, D] float32
    const int*   dur = (const int*)d_in[1];     // [B, T] int32
    float* out = (float*)d_out;                 // [B, MAXOUT, D] float32

    dim3 grid(BLOCKS_PER_BATCH, B_);
    lr_fused_kernel<<<grid, THREADS>>>(dur, (const float4*)x, (float4*)out);
}